// round 5
// baseline (speedup 1.0000x reference)
#include <cuda_runtime.h>

typedef unsigned long long u64;

// ---------- packed f32x2 helpers ----------
__device__ __forceinline__ u64 fma2(u64 a, u64 b, u64 c){
    u64 d; asm("fma.rn.f32x2 %0, %1, %2, %3;" : "=l"(d) : "l"(a), "l"(b), "l"(c)); return d;
}
__device__ __forceinline__ u64 mul2(u64 a, u64 b){
    u64 d; asm("mul.rn.f32x2 %0, %1, %2;" : "=l"(d) : "l"(a), "l"(b)); return d;
}
__device__ __forceinline__ u64 pk2(float lo, float hi){
    u64 d; asm("mov.b64 %0, {%1, %2};" : "=l"(d) : "f"(lo), "f"(hi)); return d;
}
__device__ __forceinline__ void upk2(u64 v, float& lo, float& hi){
    asm("mov.b64 {%0, %1}, %2;" : "=f"(lo), "=f"(hi) : "l"(v));
}
__device__ __forceinline__ u64 dup2(float f){ return pk2(f, f); }

// leaky_relu(x) = 0.505*x + 0.495*|x|  (slope 0.01), fully packed
__device__ __forceinline__ u64 act_lrelu(u64 v){
    u64 av = v & 0x7FFFFFFF7FFFFFFFULL;
    return fma2(av, 0x3EFD70A43EFD70A4ULL /*0.495*/, mul2(v, 0x3F0147AE3F0147AEULL /*0.505*/));
}
__device__ __forceinline__ float fast_sigmoid(float x){
    float e; asm("ex2.approx.f32 %0, %1;" : "=f"(e) : "f"(-1.44269504088896341f * x));
    float r; asm("rcp.approx.f32 %0, %1;" : "=f"(r) : "f"(1.0f + e));
    return r;
}
__device__ __forceinline__ u64 act_sig(u64 v){
    float lo, hi; upk2(v, lo, hi);
    return pk2(fast_sigmoid(lo), fast_sigmoid(hi));
}
template<int ACT> __device__ __forceinline__ u64 act(u64 v){
    return (ACT == 0) ? act_lrelu(v) : act_sig(v);
}

// ---------- one full 3-layer path ----------
// W1B: 25 pairs x 2 ulonglong2: [ (bias_pair | w_row0_pair), (w_row1_pair | pad) ]
// W2B: [bias: 5 quads][row r: 5 quads each], r = 0..49
// W3B: [bias pair][row r pair], r = 0..19   (u64 units)
template<int ACT>
__device__ __forceinline__ u64 path(const ulonglong2* __restrict__ W1B,
                                    const ulonglong2* __restrict__ W2B,
                                    const u64* __restrict__ W3B,
                                    u64 hreg)
{
    float x0, x1; upk2(hreg, x0, x1);
    u64 D0 = dup2(x0), D1 = dup2(x1);

    u64 C0, C1, C2, C3, C4, C5, C6, C7, C8, C9;
    { ulonglong2 b = W2B[0]; C0 = b.x; C1 = b.y; }
    { ulonglong2 b = W2B[1]; C2 = b.x; C3 = b.y; }
    { ulonglong2 b = W2B[2]; C4 = b.x; C5 = b.y; }
    { ulonglong2 b = W2B[3]; C6 = b.x; C7 = b.y; }
    { ulonglong2 b = W2B[4]; C8 = b.x; C9 = b.y; }

    const ulonglong2* p1 = W1B;
    const ulonglong2* p2 = W2B + 5;

    #pragma unroll 1
    for (int p = 0; p < 25; p++){
        // layer-1 output pair (outputs 2p, 2p+1)
        ulonglong2 bw = p1[0];
        u64 w1 = ((const u64*)p1)[2];
        p1 += 2;
        u64 ax = fma2(D0, bw.y, bw.x);
        ax = fma2(D1, w1, ax);
        ax = act<ACT>(ax);
        float f0, f1; upk2(ax, f0, f1);

        // scatter into layer-2 accumulators: row 2p then row 2p+1
        u64 dd = dup2(f0);
        C0 = fma2(dd, p2[0].x, C0);  C1 = fma2(dd, p2[0].y, C1);
        C2 = fma2(dd, p2[1].x, C2);  C3 = fma2(dd, p2[1].y, C3);
        C4 = fma2(dd, p2[2].x, C4);  C5 = fma2(dd, p2[2].y, C5);
        C6 = fma2(dd, p2[3].x, C6);  C7 = fma2(dd, p2[3].y, C7);
        C8 = fma2(dd, p2[4].x, C8);  C9 = fma2(dd, p2[4].y, C9);
        dd = dup2(f1);
        C0 = fma2(dd, p2[5].x, C0);  C1 = fma2(dd, p2[5].y, C1);
        C2 = fma2(dd, p2[6].x, C2);  C3 = fma2(dd, p2[6].y, C3);
        C4 = fma2(dd, p2[7].x, C4);  C5 = fma2(dd, p2[7].y, C5);
        C6 = fma2(dd, p2[8].x, C6);  C7 = fma2(dd, p2[8].y, C7);
        C8 = fma2(dd, p2[9].x, C8);  C9 = fma2(dd, p2[9].y, C9);
        p2 += 10;
    }

    C0 = act<ACT>(C0); C1 = act<ACT>(C1); C2 = act<ACT>(C2); C3 = act<ACT>(C3);
    C4 = act<ACT>(C4); C5 = act<ACT>(C5); C6 = act<ACT>(C6); C7 = act<ACT>(C7);
    C8 = act<ACT>(C8); C9 = act<ACT>(C9);

    // layer 3: 20 inputs -> 1 packed output pair
    u64 res = W3B[0];
    float lo, hi;
    upk2(C0, lo, hi); res = fma2(dup2(lo), W3B[ 1], res); res = fma2(dup2(hi), W3B[ 2], res);
    upk2(C1, lo, hi); res = fma2(dup2(lo), W3B[ 3], res); res = fma2(dup2(hi), W3B[ 4], res);
    upk2(C2, lo, hi); res = fma2(dup2(lo), W3B[ 5], res); res = fma2(dup2(hi), W3B[ 6], res);
    upk2(C3, lo, hi); res = fma2(dup2(lo), W3B[ 7], res); res = fma2(dup2(hi), W3B[ 8], res);
    upk2(C4, lo, hi); res = fma2(dup2(lo), W3B[ 9], res); res = fma2(dup2(hi), W3B[10], res);
    upk2(C5, lo, hi); res = fma2(dup2(lo), W3B[11], res); res = fma2(dup2(hi), W3B[12], res);
    upk2(C6, lo, hi); res = fma2(dup2(lo), W3B[13], res); res = fma2(dup2(hi), W3B[14], res);
    upk2(C7, lo, hi); res = fma2(dup2(lo), W3B[15], res); res = fma2(dup2(hi), W3B[16], res);
    upk2(C8, lo, hi); res = fma2(dup2(lo), W3B[17], res); res = fma2(dup2(hi), W3B[18], res);
    upk2(C9, lo, hi); res = fma2(dup2(lo), W3B[19], res); res = fma2(dup2(hi), W3B[20], res);

    return act<ACT>(res);
}

// ---------- shared fills (element-wise scalar, no per-thread arrays) ----------
// L1 block: 25 pairs x 8 floats: {b[2p],b[2p+1], W[0][2p],W[0][2p+1], W[1][2p],W[1][2p+1], 0,0}
__device__ void fill_L1(float* dstf, const float* __restrict__ W,
                        const float* __restrict__ Bv)
{
    for (int e = threadIdx.x; e < 200; e += blockDim.x){
        int p = e >> 3, k = e & 7;
        float v = 0.0f;
        if      (k < 2) v = Bv[2*p + k];
        else if (k < 4) v = W[      2*p + (k-2)];   // row 0 of W[2][50]
        else if (k < 6) v = W[50 +  2*p + (k-4)];   // row 1
        dstf[e] = v;
    }
}
// L2 block (float view): [bias: 20][row r: 20 floats], r=0..49  (exact, no padding)
__device__ void fill_L2(float* dstf, const float* __restrict__ W,
                        const float* __restrict__ Bv)
{
    for (int e = threadIdx.x; e < 1020; e += blockDim.x){
        int blk = e / 20, j = e % 20;
        dstf[e] = (blk == 0) ? Bv[j] : W[(blk - 1) * 20 + j];
    }
}
// L3 block (float view): [b0,b1][row r: W[2r], W[2r+1]], r=0..19
__device__ void fill_L3(float* dstf, const float* __restrict__ W,
                        const float* __restrict__ Bv)
{
    for (int e = threadIdx.x; e < 42; e += blockDim.x){
        int blk = e >> 1, j = e & 1;
        dstf[e] = (blk == 0) ? Bv[j] : W[(blk - 1) * 2 + j];
    }
}

// shared layout (ulonglong2 units): H1@0(50)  H2@50(255)  Z1@305(50)  Z2@355(255)
__global__ void __launch_bounds__(128)
recurrent_kernel(const float2* __restrict__ win,
                 const float* __restrict__ Wh1, const float* __restrict__ bh1,
                 const float* __restrict__ Wh2, const float* __restrict__ bh2,
                 const float* __restrict__ Wh3, const float* __restrict__ bh3,
                 const float* __restrict__ Wz1, const float* __restrict__ bz1,
                 const float* __restrict__ Wz2, const float* __restrict__ bz2,
                 const float* __restrict__ Wz3, const float* __restrict__ bz3,
                 float2* __restrict__ out, int B)
{
    __shared__ ulonglong2 sQ[610];
    __shared__ u64 sP[44];     // H3 @0 (21), Z3 @22 (21)

    fill_L1((float*)(sQ +   0), Wh1, bh1);
    fill_L2((float*)(sQ +  50), Wh2, bh2);
    fill_L1((float*)(sQ + 305), Wz1, bz1);
    fill_L2((float*)(sQ + 355), Wz2, bz2);
    fill_L3((float*)(sP +   0), Wh3, bh3);
    fill_L3((float*)(sP +  22), Wz3, bz3);
    __syncthreads();

    int tid = blockIdx.x * blockDim.x + threadIdx.x;
    if (tid >= B) return;

    float2 hin = win[tid];
    u64 hreg = pk2(hin.x, hin.y);

    float2* op = out + (size_t)tid * 19;

    #pragma unroll 1
    for (int t = 0; t < 19; t++){
        hreg     = path<0>(sQ +   0, sQ +  50, sP +  0, hreg);  // h path, leaky relu
        u64 zres = path<1>(sQ + 305, sQ + 355, sP + 22, hreg);  // z path, sigmoid
        float zlo, zhi; upk2(zres, zlo, zhi);
        op[t] = make_float2(zlo, zhi);
    }
}

extern "C" void kernel_launch(void* const* d_in, const int* in_sizes, int n_in,
                              void* d_out, int out_size)
{
    const float* w   = (const float*)d_in[0];
    const float* Wh1 = (const float*)d_in[1];
    const float* bh1 = (const float*)d_in[2];
    const float* Wh2 = (const float*)d_in[3];
    const float* bh2 = (const float*)d_in[4];
    const float* Wh3 = (const float*)d_in[5];
    const float* bh3 = (const float*)d_in[6];
    const float* Wz1 = (const float*)d_in[7];
    const float* bz1 = (const float*)d_in[8];
    const float* Wz2 = (const float*)d_in[9];
    const float* bz2 = (const float*)d_in[10];
    const float* Wz3 = (const float*)d_in[11];
    const float* bz3 = (const float*)d_in[12];

    int B = in_sizes[0] / 2;
    int threads = 128;
    int blocks = (B + threads - 1) / threads;
    recurrent_kernel<<<blocks, threads>>>((const float2*)w,
                                          Wh1, bh1, Wh2, bh2, Wh3, bh3,
                                          Wz1, bz1, Wz2, bz2, Wz3, bz3,
                                          (float2*)d_out, B);
}

// round 6
// speedup vs baseline: 1.3381x; 1.3381x over previous
#include <cuda_runtime.h>

typedef unsigned long long u64;

// ---------- packed f32x2 helpers ----------
__device__ __forceinline__ u64 fma2(u64 a, u64 b, u64 c){
    u64 d; asm("fma.rn.f32x2 %0, %1, %2, %3;" : "=l"(d) : "l"(a), "l"(b), "l"(c)); return d;
}
__device__ __forceinline__ u64 mul2(u64 a, u64 b){
    u64 d; asm("mul.rn.f32x2 %0, %1, %2;" : "=l"(d) : "l"(a), "l"(b)); return d;
}
__device__ __forceinline__ u64 pk2(float lo, float hi){
    u64 d; asm("mov.b64 %0, {%1, %2};" : "=l"(d) : "f"(lo), "f"(hi)); return d;
}
__device__ __forceinline__ void upk2(u64 v, float& lo, float& hi){
    asm("mov.b64 {%0, %1}, %2;" : "=f"(lo), "=f"(hi) : "l"(v));
}
__device__ __forceinline__ u64 dup2(float f){ return pk2(f, f); }

// leaky_relu(x) = 0.505*x + 0.495*|x|  (slope 0.01), fully packed
__device__ __forceinline__ u64 act_lrelu(u64 v){
    u64 av = v & 0x7FFFFFFF7FFFFFFFULL;
    return fma2(av, 0x3EFD70A43EFD70A4ULL /*0.495*/, mul2(v, 0x3F0147AE3F0147AEULL /*0.505*/));
}
__device__ __forceinline__ float fast_sigmoid(float x){
    float e; asm("ex2.approx.f32 %0, %1;" : "=f"(e) : "f"(-1.44269504088896341f * x));
    float r; asm("rcp.approx.f32 %0, %1;" : "=f"(r) : "f"(1.0f + e));
    return r;
}
__device__ __forceinline__ u64 act_sig(u64 v){
    float lo, hi; upk2(v, lo, hi);
    return pk2(fast_sigmoid(lo), fast_sigmoid(hi));
}
template<int ACT> __device__ __forceinline__ u64 act(u64 v){
    return (ACT == 0) ? act_lrelu(v) : act_sig(v);
}

// scatter one loaded quad into both items' accumulator pairs
#define SCAT(qv, a0, a1) \
    CA##a0 = fma2(ddA, (qv).x, CA##a0);  CB##a0 = fma2(ddB, (qv).x, CB##a0); \
    CA##a1 = fma2(ddA, (qv).y, CA##a1);  CB##a1 = fma2(ddB, (qv).y, CB##a1);

// layer-3 step for one accumulator pair (rows 2i, 2i+1), both items
#define L3STEP(Ci, wlo_idx) { \
    float loA, hiA, loB, hiB; \
    upk2(CA##Ci, loA, hiA); upk2(CB##Ci, loB, hiB); \
    u64 wl = W3B[wlo_idx], wh = W3B[(wlo_idx)+1]; \
    resA = fma2(dup2(loA), wl, resA);  resB = fma2(dup2(loB), wl, resB); \
    resA = fma2(dup2(hiA), wh, resA);  resB = fma2(dup2(hiB), wh, resB); }

// ---------- one full 3-layer path, two batch items at once ----------
// W1B: 25 pairs x 2 ulonglong2: [ (bias_pair | w_row0_pair), (w_row1_pair | pad) ]
// W2B: [bias: 5 quads][row r: 5 quads each], r = 0..49
// W3B: [bias pair][row r pair], r = 0..19   (u64 units)
template<int ACT>
__device__ __forceinline__ void path2(const ulonglong2* __restrict__ W1B,
                                      const ulonglong2* __restrict__ W2B,
                                      const u64* __restrict__ W3B,
                                      u64& hA, u64& hB)
{
    float xa0, xa1, xb0, xb1;
    upk2(hA, xa0, xa1); upk2(hB, xb0, xb1);
    u64 D0A = dup2(xa0), D1A = dup2(xa1);
    u64 D0B = dup2(xb0), D1B = dup2(xb1);

    u64 CA0, CA1, CA2, CA3, CA4, CA5, CA6, CA7, CA8, CA9;
    u64 CB0, CB1, CB2, CB3, CB4, CB5, CB6, CB7, CB8, CB9;
    { ulonglong2 b = W2B[0]; CA0 = b.x; CA1 = b.y; CB0 = b.x; CB1 = b.y; }
    { ulonglong2 b = W2B[1]; CA2 = b.x; CA3 = b.y; CB2 = b.x; CB3 = b.y; }
    { ulonglong2 b = W2B[2]; CA4 = b.x; CA5 = b.y; CB4 = b.x; CB5 = b.y; }
    { ulonglong2 b = W2B[3]; CA6 = b.x; CA7 = b.y; CB6 = b.x; CB7 = b.y; }
    { ulonglong2 b = W2B[4]; CA8 = b.x; CA9 = b.y; CB8 = b.x; CB9 = b.y; }

    const ulonglong2* p1 = W1B;
    const ulonglong2* p2 = W2B + 5;

    #pragma unroll 1
    for (int p = 0; p < 25; p++){
        // layer-1 output pair (outputs 2p, 2p+1) for both items
        ulonglong2 bw = p1[0];
        u64 w1 = ((const u64*)p1)[2];
        p1 += 2;
        u64 axA = fma2(D0A, bw.y, bw.x); axA = fma2(D1A, w1, axA); axA = act<ACT>(axA);
        u64 axB = fma2(D0B, bw.y, bw.x); axB = fma2(D1B, w1, axB); axB = act<ACT>(axB);
        float f0A, f1A, f0B, f1B;
        upk2(axA, f0A, f1A); upk2(axB, f0B, f1B);

        // scatter row 2p
        {
            u64 ddA = dup2(f0A), ddB = dup2(f0B);
            ulonglong2 q;
            q = p2[0]; SCAT(q, 0, 1)
            q = p2[1]; SCAT(q, 2, 3)
            q = p2[2]; SCAT(q, 4, 5)
            q = p2[3]; SCAT(q, 6, 7)
            q = p2[4]; SCAT(q, 8, 9)
        }
        // scatter row 2p+1
        {
            u64 ddA = dup2(f1A), ddB = dup2(f1B);
            ulonglong2 q;
            q = p2[5]; SCAT(q, 0, 1)
            q = p2[6]; SCAT(q, 2, 3)
            q = p2[7]; SCAT(q, 4, 5)
            q = p2[8]; SCAT(q, 6, 7)
            q = p2[9]; SCAT(q, 8, 9)
        }
        p2 += 10;
    }

    CA0 = act<ACT>(CA0); CA1 = act<ACT>(CA1); CA2 = act<ACT>(CA2); CA3 = act<ACT>(CA3);
    CA4 = act<ACT>(CA4); CA5 = act<ACT>(CA5); CA6 = act<ACT>(CA6); CA7 = act<ACT>(CA7);
    CA8 = act<ACT>(CA8); CA9 = act<ACT>(CA9);
    CB0 = act<ACT>(CB0); CB1 = act<ACT>(CB1); CB2 = act<ACT>(CB2); CB3 = act<ACT>(CB3);
    CB4 = act<ACT>(CB4); CB5 = act<ACT>(CB5); CB6 = act<ACT>(CB6); CB7 = act<ACT>(CB7);
    CB8 = act<ACT>(CB8); CB9 = act<ACT>(CB9);

    // layer 3: 20 inputs -> 1 packed output pair, both items
    u64 resA = W3B[0];
    u64 resB = resA;
    L3STEP(0,  1)
    L3STEP(1,  3)
    L3STEP(2,  5)
    L3STEP(3,  7)
    L3STEP(4,  9)
    L3STEP(5, 11)
    L3STEP(6, 13)
    L3STEP(7, 15)
    L3STEP(8, 17)
    L3STEP(9, 19)

    hA = act<ACT>(resA);
    hB = act<ACT>(resB);
}

// ---------- shared fills (element-wise scalar, no per-thread arrays) ----------
// L1 block: 25 pairs x 8 floats: {b[2p],b[2p+1], W[0][2p],W[0][2p+1], W[1][2p],W[1][2p+1], 0,0}
__device__ void fill_L1(float* dstf, const float* __restrict__ W,
                        const float* __restrict__ Bv)
{
    for (int e = threadIdx.x; e < 200; e += blockDim.x){
        int p = e >> 3, k = e & 7;
        float v = 0.0f;
        if      (k < 2) v = Bv[2*p + k];
        else if (k < 4) v = W[      2*p + (k-2)];   // row 0 of W[2][50]
        else if (k < 6) v = W[50 +  2*p + (k-4)];   // row 1
        dstf[e] = v;
    }
}
// L2 block (float view): [bias: 20][row r: 20 floats], r=0..49
__device__ void fill_L2(float* dstf, const float* __restrict__ W,
                        const float* __restrict__ Bv)
{
    for (int e = threadIdx.x; e < 1020; e += blockDim.x){
        int blk = e / 20, j = e % 20;
        dstf[e] = (blk == 0) ? Bv[j] : W[(blk - 1) * 20 + j];
    }
}
// L3 block (float view): [b0,b1][row r: W[2r], W[2r+1]], r=0..19
__device__ void fill_L3(float* dstf, const float* __restrict__ W,
                        const float* __restrict__ Bv)
{
    for (int e = threadIdx.x; e < 42; e += blockDim.x){
        int blk = e >> 1, j = e & 1;
        dstf[e] = (blk == 0) ? Bv[j] : W[(blk - 1) * 2 + j];
    }
}

// shared layout (ulonglong2 units): H1@0(50)  H2@50(255)  Z1@305(50)  Z2@355(255)
__global__ void __launch_bounds__(128)
recurrent_kernel(const float2* __restrict__ win,
                 const float* __restrict__ Wh1, const float* __restrict__ bh1,
                 const float* __restrict__ Wh2, const float* __restrict__ bh2,
                 const float* __restrict__ Wh3, const float* __restrict__ bh3,
                 const float* __restrict__ Wz1, const float* __restrict__ bz1,
                 const float* __restrict__ Wz2, const float* __restrict__ bz2,
                 const float* __restrict__ Wz3, const float* __restrict__ bz3,
                 float2* __restrict__ out, int half)
{
    __shared__ ulonglong2 sQ[610];
    __shared__ u64 sP[44];     // H3 @0 (21), Z3 @22 (21)

    fill_L1((float*)(sQ +   0), Wh1, bh1);
    fill_L2((float*)(sQ +  50), Wh2, bh2);
    fill_L1((float*)(sQ + 305), Wz1, bz1);
    fill_L2((float*)(sQ + 355), Wz2, bz2);
    fill_L3((float*)(sP +   0), Wh3, bh3);
    fill_L3((float*)(sP +  22), Wz3, bz3);
    __syncthreads();

    int tid = blockIdx.x * blockDim.x + threadIdx.x;
    if (tid >= half) return;

    float2 hinA = win[tid];
    float2 hinB = win[tid + half];
    u64 hA = pk2(hinA.x, hinA.y);
    u64 hB = pk2(hinB.x, hinB.y);

    float2* opA = out + (size_t)tid * 19;
    float2* opB = out + ((size_t)tid + half) * 19;

    #pragma unroll 1
    for (int t = 0; t < 19; t++){
        path2<0>(sQ +   0, sQ +  50, sP +  0, hA, hB);   // h path, leaky relu (updates hA,hB)
        u64 zA = hA, zB = hB;
        path2<1>(sQ + 305, sQ + 355, sP + 22, zA, zB);   // z path, sigmoid
        float lo, hi;
        upk2(zA, lo, hi); opA[t] = make_float2(lo, hi);
        upk2(zB, lo, hi); opB[t] = make_float2(lo, hi);
    }
}

extern "C" void kernel_launch(void* const* d_in, const int* in_sizes, int n_in,
                              void* d_out, int out_size)
{
    const float* w   = (const float*)d_in[0];
    const float* Wh1 = (const float*)d_in[1];
    const float* bh1 = (const float*)d_in[2];
    const float* Wh2 = (const float*)d_in[3];
    const float* bh2 = (const float*)d_in[4];
    const float* Wh3 = (const float*)d_in[5];
    const float* bh3 = (const float*)d_in[6];
    const float* Wz1 = (const float*)d_in[7];
    const float* bz1 = (const float*)d_in[8];
    const float* Wz2 = (const float*)d_in[9];
    const float* bz2 = (const float*)d_in[10];
    const float* Wz3 = (const float*)d_in[11];
    const float* bz3 = (const float*)d_in[12];

    int B = in_sizes[0] / 2;
    int half = B / 2;                 // B = 1048576, even
    int threads = 128;
    int blocks = (half + threads - 1) / threads;
    recurrent_kernel<<<blocks, threads>>>((const float2*)w,
                                          Wh1, bh1, Wh2, bh2, Wh3, bh3,
                                          Wz1, bz1, Wz2, bz2, Wz3, bz3,
                                          (float2*)d_out, half);
}